// round 1
// baseline (speedup 1.0000x reference)
#include <cuda_runtime.h>
#include <math.h>

#define B 2
#define L 2048
#define DIMM 1024
#define H 16
#define DH 64
#define BH (B*H)      // 32
#define TOK (B*L)     // 4096

// ---------------- scratch (static device globals; no allocs) ----------------
__device__ float g_qk[BH*L*DH];          // (b,h,l,d) 16 MB
__device__ float g_v [BH*L*DH];          // (b,h,l,d) 16 MB
__device__ float g_dot[BH*L];
__device__ float g_norm2[BH*L];
__device__ unsigned int g_maxn2[BH];     // float bits (>=0 so uint-monotonic)
__device__ unsigned char g_hq[BH*L];
__device__ unsigned char g_hk[BH*L];

// ---------------- projection GEMM: C = X @ W^T + b, split to heads ----------
#define PBM 64
#define PBN 64
#define PBK 16

__global__ void proj_kernel(const float* __restrict__ X,
                            const float* __restrict__ Wq, const float* __restrict__ bq,
                            const float* __restrict__ Wv, const float* __restrict__ bv)
{
    __shared__ float Xs[PBK][PBM+1];
    __shared__ float Ws[PBK][PBN+1];
    const float* W    = blockIdx.z ? Wv : Wq;
    const float* bias = blockIdx.z ? bv : bq;
    float* out        = blockIdx.z ? g_v : g_qk;
    const int m0 = blockIdx.y * PBM;
    const int n0 = blockIdx.x * PBN;
    const int tid = threadIdx.x;
    const int tx = tid & 15, ty = tid >> 4;
    const int lr = tid >> 2;           // 0..63
    const int lc = (tid & 3) * 4;      // 0,4,8,12

    float acc[4][4] = {};

    for (int kk = 0; kk < DIMM; kk += PBK) {
        float4 xa = *(const float4*)&X[(size_t)(m0+lr)*DIMM + kk + lc];
        float4 wa = *(const float4*)&W[(size_t)(n0+lr)*DIMM + kk + lc];
        Xs[lc+0][lr]=xa.x; Xs[lc+1][lr]=xa.y; Xs[lc+2][lr]=xa.z; Xs[lc+3][lr]=xa.w;
        Ws[lc+0][lr]=wa.x; Ws[lc+1][lr]=wa.y; Ws[lc+2][lr]=wa.z; Ws[lc+3][lr]=wa.w;
        __syncthreads();
        #pragma unroll
        for (int k = 0; k < PBK; k++) {
            float a[4], bb[4];
            #pragma unroll
            for (int i=0;i<4;i++) a[i]  = Xs[k][ty*4+i];
            #pragma unroll
            for (int j=0;j<4;j++) bb[j] = Ws[k][tx*4+j];
            #pragma unroll
            for (int i=0;i<4;i++)
                #pragma unroll
                for (int j=0;j<4;j++)
                    acc[i][j] = fmaf(a[i], bb[j], acc[i][j]);
        }
        __syncthreads();
    }

    #pragma unroll
    for (int i=0;i<4;i++){
        int m = m0 + ty*4 + i;
        int b = m >> 11, l = m & (L-1);
        #pragma unroll
        for (int j=0;j<4;j++){
            int n = n0 + tx*4 + j;
            int h = n >> 6, d = n & 63;
            out[(((size_t)(b*H + h)*L + l)*DH) + d] = acc[i][j] + bias[n];
        }
    }
}

// ---------------- hash pipeline ----------------
__global__ void init_maxn_kernel() {
    if (threadIdx.x < BH) g_maxn2[threadIdx.x] = 0u;
}

// one warp per token: dot(q, a[:64]) and ||q||^2, atomicMax of norm2 per (b,h)
__global__ void hash1_kernel(const float* __restrict__ ha) {
    int gw = (blockIdx.x * blockDim.x + threadIdx.x) >> 5;
    int lane = threadIdx.x & 31;
    if (gw >= BH*L) return;
    const float* q = &g_qk[(size_t)gw * DH];
    float v0 = q[lane], v1 = q[lane+32];
    float dot = v0*ha[lane] + v1*ha[lane+32];
    float n2  = v0*v0 + v1*v1;
    #pragma unroll
    for (int o=16;o;o>>=1){
        dot += __shfl_xor_sync(0xffffffffu, dot, o);
        n2  += __shfl_xor_sync(0xffffffffu, n2,  o);
    }
    if (lane == 0) {
        g_dot[gw] = dot;
        g_norm2[gw] = n2;
        atomicMax(&g_maxn2[gw >> 11], __float_as_uint(n2));   // gw/L -> (b,h)
    }
}

__global__ void hash2_kernel(const float* __restrict__ ha) {
    int t = blockIdx.x * blockDim.x + threadIdx.x;
    if (t >= BH*L) return;
    float dot = g_dot[t], n2 = g_norm2[t];
    float maxn = sqrtf(__uint_as_float(g_maxn2[t >> 11]));
    float s = 0.75f / fmaxf(maxn, 1e-12f);
    float nk2 = s*s*n2;
    float hkval = s*dot + (0.5f - nk2)*ha[DH] + (0.5f - nk2*nk2)*ha[DH+1];
    // hq = sign(q.a / ||q||) >= 0  <=>  dot >= 0
    g_hq[t] = (dot   >= 0.0f) ? 1 : 0;
    g_hk[t] = (hkval >= 0.0f) ? 1 : 0;
}

// ---------------- fused flash-style attention ----------------
#define AB 64
#define APAD 4
#define ASTR (AB+APAD)   // 68

__device__ __forceinline__ float rmax16(float v){
    #pragma unroll
    for (int o=8;o;o>>=1) v = fmaxf(v, __shfl_xor_sync(0xffffffffu, v, o, 16));
    return v;
}
__device__ __forceinline__ float rsum16(float v){
    #pragma unroll
    for (int o=8;o;o>>=1) v += __shfl_xor_sync(0xffffffffu, v, o, 16);
    return v;
}

__global__ void attn_kernel(float* __restrict__ out) {
    extern __shared__ float sm[];
    float (*Qt)[ASTR] = (float(*)[ASTR])(sm);              // [d][i] transposed
    float (*Kt)[ASTR] = (float(*)[ASTR])(sm + 1*AB*ASTR);  // [d][j] transposed
    float (*Vs)[ASTR] = (float(*)[ASTR])(sm + 2*AB*ASTR);  // [j][d]
    float (*Ps)[ASTR] = (float(*)[ASTR])(sm + 3*AB*ASTR);  // [i][j]

    const int bh = blockIdx.y;
    const int q0 = blockIdx.x * AB;
    const int tid = threadIdx.x;
    const int tx = tid & 15, ty = tid >> 4;
    const int lr = tid >> 2;           // 0..63
    const int lc = (tid & 3) * 4;      // 0,4,8,12

    // load Q tile transposed
    const float* qbase = &g_qk[((size_t)bh*L + q0)*DH];
    #pragma unroll
    for (int c0 = 0; c0 < DH; c0 += 16) {
        float4 a = *(const float4*)&qbase[(size_t)lr*DH + c0 + lc];
        Qt[c0+lc+0][lr]=a.x; Qt[c0+lc+1][lr]=a.y; Qt[c0+lc+2][lr]=a.z; Qt[c0+lc+3][lr]=a.w;
    }

    unsigned char hqv[4];
    #pragma unroll
    for (int i=0;i<4;i++) hqv[i] = g_hq[(size_t)bh*L + q0 + ty*4 + i];

    float O[4][4] = {};
    float mrow[4], lrow[4];
    #pragma unroll
    for (int i=0;i<4;i++){ mrow[i] = -INFINITY; lrow[i] = 0.0f; }

    const float scale = 0.125f;   // 1/sqrt(64)

    for (int k0 = 0; k0 < L; k0 += AB) {
        const float* kbase = &g_qk[((size_t)bh*L + k0)*DH];
        const float* vbase = &g_v [((size_t)bh*L + k0)*DH];
        __syncthreads();   // protect Kt/Vs/Ps from previous iter readers
        #pragma unroll
        for (int c0 = 0; c0 < DH; c0 += 16) {
            float4 a = *(const float4*)&kbase[(size_t)lr*DH + c0 + lc];
            Kt[c0+lc+0][lr]=a.x; Kt[c0+lc+1][lr]=a.y; Kt[c0+lc+2][lr]=a.z; Kt[c0+lc+3][lr]=a.w;
            float4 b = *(const float4*)&vbase[(size_t)lr*DH + c0 + lc];
            *(float4*)&Vs[lr][c0+lc] = b;
        }
        __syncthreads();

        // S = Q @ K^T
        float acc[4][4] = {};
        #pragma unroll 8
        for (int d = 0; d < DH; d++) {
            float4 a4 = *(const float4*)&Qt[d][ty*4];
            float4 b4 = *(const float4*)&Kt[d][tx*4];
            float a[4] = {a4.x,a4.y,a4.z,a4.w};
            float bb[4] = {b4.x,b4.y,b4.z,b4.w};
            #pragma unroll
            for (int i=0;i<4;i++)
                #pragma unroll
                for (int j=0;j<4;j++)
                    acc[i][j] = fmaf(a[i], bb[j], acc[i][j]);
        }

        // mask + scale
        unsigned char hkv[4];
        #pragma unroll
        for (int j=0;j<4;j++) hkv[j] = g_hk[(size_t)bh*L + k0 + tx*4 + j];
        float sc[4][4];
        #pragma unroll
        for (int i=0;i<4;i++)
            #pragma unroll
            for (int j=0;j<4;j++)
                sc[i][j] = acc[i][j]*scale + ((hqv[i]==hkv[j]) ? 0.0f : -1e4f);

        // online softmax per row (16-lane groups share a row set)
        float corr[4];
        #pragma unroll
        for (int i=0;i<4;i++) {
            float m = fmaxf(fmaxf(sc[i][0], sc[i][1]), fmaxf(sc[i][2], sc[i][3]));
            m = rmax16(m);
            float mnew = fmaxf(mrow[i], m);
            corr[i] = expf(mrow[i] - mnew);     // first tile: exp(-inf) = 0
            float rs = 0.0f;
            float p0 = expf(sc[i][0] - mnew);
            float p1 = expf(sc[i][1] - mnew);
            float p2 = expf(sc[i][2] - mnew);
            float p3 = expf(sc[i][3] - mnew);
            rs = p0 + p1 + p2 + p3;
            rs = rsum16(rs);
            lrow[i] = lrow[i]*corr[i] + rs;
            mrow[i] = mnew;
            Ps[ty*4+i][tx*4+0] = p0;
            Ps[ty*4+i][tx*4+1] = p1;
            Ps[ty*4+i][tx*4+2] = p2;
            Ps[ty*4+i][tx*4+3] = p3;
        }
        #pragma unroll
        for (int i=0;i<4;i++)
            #pragma unroll
            for (int dd=0;dd<4;dd++)
                O[i][dd] *= corr[i];

        __syncthreads();

        // O += P @ V
        #pragma unroll 8
        for (int j = 0; j < AB; j++) {
            float4 v4 = *(const float4*)&Vs[j][tx*4];
            float vv[4] = {v4.x, v4.y, v4.z, v4.w};
            float pp[4];
            #pragma unroll
            for (int i=0;i<4;i++) pp[i] = Ps[ty*4+i][j];
            #pragma unroll
            for (int i=0;i<4;i++)
                #pragma unroll
                for (int dd=0;dd<4;dd++)
                    O[i][dd] = fmaf(pp[i], vv[dd], O[i][dd]);
        }
    }

    // epilogue: normalize, write (b, l, h*DH+d)
    const int b = bh >> 4, h = bh & 15;
    #pragma unroll
    for (int i=0;i<4;i++) {
        float inv = 1.0f / lrow[i];
        int l = q0 + ty*4 + i;
        size_t base = ((size_t)b*L + l)*DIMM + h*DH + tx*4;
        #pragma unroll
        for (int dd=0;dd<4;dd++)
            out[base + dd] = O[i][dd] * inv;
    }
}

// ---------------- launch ----------------
extern "C" void kernel_launch(void* const* d_in, const int* in_sizes, int n_in,
                              void* d_out, int out_size) {
    const float* X  = (const float*)d_in[0];
    const float* Wq = (const float*)d_in[1];
    const float* bq = (const float*)d_in[2];
    const float* Wv = (const float*)d_in[3];
    const float* bv = (const float*)d_in[4];
    const float* ha = (const float*)d_in[5];
    float* out = (float*)d_out;

    dim3 pg(DIMM/PBN, TOK/PBM, 2);
    proj_kernel<<<pg, 256>>>(X, Wq, bq, Wv, bv);

    init_maxn_kernel<<<1, 32>>>();
    hash1_kernel<<<(BH*L*32)/256, 256>>>(ha);
    hash2_kernel<<<(BH*L)/256, 256>>>(ha);

    const int ASM = 4 * AB * ASTR * (int)sizeof(float);   // 69,632 B
    cudaFuncSetAttribute(attn_kernel, cudaFuncAttributeMaxDynamicSharedMemorySize, ASM);
    dim3 ag(L/AB, BH);
    attn_kernel<<<ag, 256, ASM>>>(out);
}

// round 2
// speedup vs baseline: 1.0365x; 1.0365x over previous
#include <cuda_runtime.h>
#include <math.h>

#define B 2
#define L 2048
#define DIMM 1024
#define H 16
#define DH 64
#define BH (B*H)      // 32
#define TOK (B*L)     // 4096

typedef unsigned long long ull;

#define FMA2(d_, a_, b_, c_) asm("fma.rn.f32x2 %0, %1, %2, %3;" : "=l"(d_) : "l"(a_), "l"(b_), "l"(c_))
#define MUL2(d_, a_, b_)     asm("mul.rn.f32x2 %0, %1, %2;"     : "=l"(d_) : "l"(a_), "l"(b_))
#define PACK2(d_, lo_, hi_)  asm("mov.b64 %0, {%1, %2};"        : "=l"(d_) : "f"(lo_), "f"(hi_))
#define UNPACK2(lo_, hi_, s_) asm("mov.b64 {%0, %1}, %2;"       : "=f"(lo_), "=f"(hi_) : "l"(s_))

// ---------------- scratch (static device globals; no allocs) ----------------
__device__ float g_qk[BH*L*DH];          // (b,h,l,d)
__device__ float g_v [BH*L*DH];          // (b,h,l,d)
__device__ float g_dot[BH*L];
__device__ float g_norm2[BH*L];
__device__ unsigned int g_maxn2[BH];
__device__ unsigned char g_hq[BH*L];
__device__ unsigned char g_hk[BH*L];

// ============ projection GEMM: C = X @ W^T + b, split to heads ============
// tile M=128 tokens x N=64 features, 128 threads, 8x8 per thread, f32x2
#define PBK 16

__global__ __launch_bounds__(128)
void proj_kernel(const float* __restrict__ X,
                 const float* __restrict__ Wq, const float* __restrict__ bq,
                 const float* __restrict__ Wv, const float* __restrict__ bv)
{
    __shared__ float Xt[PBK][132];   // [k][m] transposed
    __shared__ float Wt[PBK][68];    // [k][n] transposed

    const float* W    = blockIdx.z ? Wv : Wq;
    const float* bias = blockIdx.z ? bv : bq;
    float* out        = blockIdx.z ? g_v : g_qk;

    const int m0 = blockIdx.y * 128;
    const int n0 = blockIdx.x * 64;
    const int tid = threadIdx.x;
    const int tx = tid & 7, ty = tid >> 3;

    ull acc[8][4];
    #pragma unroll
    for (int i=0;i<8;i++)
        #pragma unroll
        for (int j=0;j<4;j++) acc[i][j] = 0ull;

    const int wn = tid >> 1;          // 0..63
    const int wk = (tid & 1) * 8;     // 0 or 8

    for (int kk = 0; kk < DIMM; kk += PBK) {
        __syncthreads();
        // load X chunk transposed: thread tid handles token row m0+tid
        {
            const float* xp = &X[(size_t)(m0+tid)*DIMM + kk];
            #pragma unroll
            for (int c4 = 0; c4 < 4; c4++) {
                float4 a = *(const float4*)&xp[c4*4];
                Xt[c4*4+0][tid]=a.x; Xt[c4*4+1][tid]=a.y;
                Xt[c4*4+2][tid]=a.z; Xt[c4*4+3][tid]=a.w;
            }
        }
        // load W chunk transposed: thread handles (n=wn, k half wk)
        {
            const float* wp = &W[(size_t)(n0+wn)*DIMM + kk + wk];
            #pragma unroll
            for (int c4 = 0; c4 < 2; c4++) {
                float4 a = *(const float4*)&wp[c4*4];
                Wt[wk+c4*4+0][wn]=a.x; Wt[wk+c4*4+1][wn]=a.y;
                Wt[wk+c4*4+2][wn]=a.z; Wt[wk+c4*4+3][wn]=a.w;
            }
        }
        __syncthreads();

        #pragma unroll
        for (int k = 0; k < PBK; k++) {
            float4 a0 = *(const float4*)&Xt[k][ty*8];
            float4 a1 = *(const float4*)&Xt[k][ty*8+4];
            ulonglong2 b0 = *(const ulonglong2*)&Wt[k][tx*8];
            ulonglong2 b1 = *(const ulonglong2*)&Wt[k][tx*8+4];
            ull bp[4] = {b0.x, b0.y, b1.x, b1.y};
            float av[8] = {a0.x,a0.y,a0.z,a0.w,a1.x,a1.y,a1.z,a1.w};
            #pragma unroll
            for (int i=0;i<8;i++){
                ull ad; PACK2(ad, av[i], av[i]);
                #pragma unroll
                for (int j=0;j<4;j++) FMA2(acc[i][j], ad, bp[j], acc[i][j]);
            }
        }
    }

    // epilogue: n-range is within one head (n0 aligned to 64)
    const int hh = n0 >> 6;
    #pragma unroll
    for (int i=0;i<8;i++){
        int m = m0 + ty*8 + i;
        int bb = m >> 11, ll = m & (L-1);
        float o[8];
        #pragma unroll
        for (int j=0;j<4;j++){
            float lo, hi; UNPACK2(lo, hi, acc[i][j]);
            o[2*j]   = lo + bias[n0 + tx*8 + 2*j];
            o[2*j+1] = hi + bias[n0 + tx*8 + 2*j+1];
        }
        float* op = &out[(((size_t)(bb*H + hh)*L + ll)*DH) + tx*8];
        *(float4*)&op[0] = make_float4(o[0],o[1],o[2],o[3]);
        *(float4*)&op[4] = make_float4(o[4],o[5],o[6],o[7]);
    }
}

// ---------------- hash pipeline ----------------
__global__ void init_maxn_kernel() {
    if (threadIdx.x < BH) g_maxn2[threadIdx.x] = 0u;
}

__global__ void hash1_kernel(const float* __restrict__ ha) {
    int gw = (blockIdx.x * blockDim.x + threadIdx.x) >> 5;
    int lane = threadIdx.x & 31;
    if (gw >= BH*L) return;
    const float* q = &g_qk[(size_t)gw * DH];
    float v0 = q[lane], v1 = q[lane+32];
    float dot = v0*ha[lane] + v1*ha[lane+32];
    float n2  = v0*v0 + v1*v1;
    #pragma unroll
    for (int o=16;o;o>>=1){
        dot += __shfl_xor_sync(0xffffffffu, dot, o);
        n2  += __shfl_xor_sync(0xffffffffu, n2,  o);
    }
    if (lane == 0) {
        g_dot[gw] = dot;
        g_norm2[gw] = n2;
        atomicMax(&g_maxn2[gw >> 11], __float_as_uint(n2));
    }
}

__global__ void hash2_kernel(const float* __restrict__ ha) {
    int t = blockIdx.x * blockDim.x + threadIdx.x;
    if (t >= BH*L) return;
    float dot = g_dot[t], n2 = g_norm2[t];
    float maxn = sqrtf(__uint_as_float(g_maxn2[t >> 11]));
    float s = 0.75f / fmaxf(maxn, 1e-12f);
    float nk2 = s*s*n2;
    float hkval = s*dot + (0.5f - nk2)*ha[DH] + (0.5f - nk2*nk2)*ha[DH+1];
    g_hq[t] = (dot   >= 0.0f) ? 1 : 0;
    g_hk[t] = (hkval >= 0.0f) ? 1 : 0;
}

// ============ fused flash attention: 128x64 tiles, 8x8/thread, f32x2 ============
#define AM 128
#define AN 64
#define QSTR 132
#define KSTR 68

#define QT_OFF 0
#define KT_OFF (64*QSTR)                 // 8448
#define VS_OFF (KT_OFF + 64*KSTR)        // 12800
#define PS_OFF (VS_OFF + 64*KSTR)        // 17152
#define ATTN_SM_FLOATS (PS_OFF + 128*KSTR)  // 25856
#define ATTN_SM_BYTES (ATTN_SM_FLOATS*4)

__global__ __launch_bounds__(128, 2)
void attn_kernel(float* __restrict__ out) {
    extern __shared__ float sm[];
    float (*Qt)[QSTR] = (float(*)[QSTR])(sm + QT_OFF);   // [d][i]
    float (*Kt)[KSTR] = (float(*)[KSTR])(sm + KT_OFF);   // [d][j]
    float (*Vs)[KSTR] = (float(*)[KSTR])(sm + VS_OFF);   // [j][d]
    float (*Ps)[KSTR] = (float(*)[KSTR])(sm + PS_OFF);   // [i][j]

    const int bh = blockIdx.y;
    const int q0 = blockIdx.x * AM;
    const int tid = threadIdx.x;
    const int tx = tid & 7, ty = tid >> 3;

    // load Q tile transposed: thread tid owns query row q0+tid
    {
        const float* qp = &g_qk[((size_t)bh*L + q0 + tid)*DH];
        #pragma unroll
        for (int c4 = 0; c4 < 16; c4++) {
            float4 a = *(const float4*)&qp[c4*4];
            Qt[c4*4+0][tid]=a.x; Qt[c4*4+1][tid]=a.y;
            Qt[c4*4+2][tid]=a.z; Qt[c4*4+3][tid]=a.w;
        }
    }

    // hash bits for my 8 query rows
    ull hq8 = *(const ull*)&g_hq[(size_t)bh*L + q0 + ty*8];

    ull O2[8][4];
    float mrow[8], lrow[8];
    #pragma unroll
    for (int i=0;i<8;i++){
        mrow[i] = -INFINITY; lrow[i] = 0.0f;
        #pragma unroll
        for (int p=0;p<4;p++) O2[i][p] = 0ull;
    }

    const int kvrow = tid >> 1;            // 0..63
    const int kvhalf = (tid & 1) * 32;     // 0 or 32

    for (int k0 = 0; k0 < L; k0 += AN) {
        __syncthreads();
        // load K transposed + V natural
        {
            const float* kp = &g_qk[((size_t)bh*L + k0 + kvrow)*DH + kvhalf];
            const float* vp = &g_v [((size_t)bh*L + k0 + kvrow)*DH + kvhalf];
            #pragma unroll
            for (int c4 = 0; c4 < 8; c4++) {
                float4 a = *(const float4*)&kp[c4*4];
                Kt[kvhalf+c4*4+0][kvrow]=a.x; Kt[kvhalf+c4*4+1][kvrow]=a.y;
                Kt[kvhalf+c4*4+2][kvrow]=a.z; Kt[kvhalf+c4*4+3][kvrow]=a.w;
                *(float4*)&Vs[kvrow][kvhalf+c4*4] = *(const float4*)&vp[c4*4];
            }
        }
        __syncthreads();

        // ---- S = Q @ K^T (packed along j) ----
        ull acc[8][4];
        #pragma unroll
        for (int i=0;i<8;i++)
            #pragma unroll
            for (int j=0;j<4;j++) acc[i][j] = 0ull;

        #pragma unroll 4
        for (int d = 0; d < DH; d++) {
            float4 a0 = *(const float4*)&Qt[d][ty*8];
            float4 a1 = *(const float4*)&Qt[d][ty*8+4];
            ulonglong2 b0 = *(const ulonglong2*)&Kt[d][tx*8];
            ulonglong2 b1 = *(const ulonglong2*)&Kt[d][tx*8+4];
            ull bp[4] = {b0.x, b0.y, b1.x, b1.y};
            float av[8] = {a0.x,a0.y,a0.z,a0.w,a1.x,a1.y,a1.z,a1.w};
            #pragma unroll
            for (int i=0;i<8;i++){
                ull ad; PACK2(ad, av[i], av[i]);
                #pragma unroll
                for (int j=0;j<4;j++) FMA2(acc[i][j], ad, bp[j], acc[i][j]);
            }
        }

        // ---- mask + online softmax ----
        ull hk8 = *(const ull*)&g_hk[(size_t)bh*L + k0 + tx*8];
        #pragma unroll
        for (int i=0;i<8;i++){
            unsigned int hqi = (unsigned int)(hq8 >> (8*i)) & 1u;
            float s[8];
            #pragma unroll
            for (int p=0;p<4;p++){
                float lo, hi; UNPACK2(lo, hi, acc[i][p]);
                s[2*p] = lo; s[2*p+1] = hi;
            }
            #pragma unroll
            for (int j=0;j<8;j++){
                unsigned int hkj = (unsigned int)(hk8 >> (8*j)) & 1u;
                s[j] = fmaf(s[j], 0.125f, (hqi ^ hkj) ? -1e4f : 0.0f);
            }
            float m = s[0];
            #pragma unroll
            for (int j=1;j<8;j++) m = fmaxf(m, s[j]);
            #pragma unroll
            for (int o=4;o;o>>=1) m = fmaxf(m, __shfl_xor_sync(0xffffffffu, m, o, 8));
            float mnew = fmaxf(mrow[i], m);
            float corr = __expf(mrow[i] - mnew);
            mrow[i] = mnew;
            float rs = 0.0f;
            float p8[8];
            #pragma unroll
            for (int j=0;j<8;j++){ p8[j] = __expf(s[j] - mnew); rs += p8[j]; }
            #pragma unroll
            for (int o=4;o;o>>=1) rs += __shfl_xor_sync(0xffffffffu, rs, o, 8);
            lrow[i] = lrow[i]*corr + rs;
            // rescale O
            ull cd; PACK2(cd, corr, corr);
            #pragma unroll
            for (int p=0;p<4;p++) MUL2(O2[i][p], O2[i][p], cd);
            // stage P
            *(float4*)&Ps[ty*8+i][tx*8]   = make_float4(p8[0],p8[1],p8[2],p8[3]);
            *(float4*)&Ps[ty*8+i][tx*8+4] = make_float4(p8[4],p8[5],p8[6],p8[7]);
        }
        __syncthreads();

        // ---- O += P @ V (P dup'd, packed along d) ----
        #pragma unroll 2
        for (int jj = 0; jj < AN; jj += 4) {
            float pbuf[8][4];
            #pragma unroll
            for (int i=0;i<8;i++){
                float4 t = *(const float4*)&Ps[ty*8+i][jj];
                pbuf[i][0]=t.x; pbuf[i][1]=t.y; pbuf[i][2]=t.z; pbuf[i][3]=t.w;
            }
            #pragma unroll
            for (int jo=0;jo<4;jo++){
                ulonglong2 v0 = *(const ulonglong2*)&Vs[jj+jo][tx*8];
                ulonglong2 v1 = *(const ulonglong2*)&Vs[jj+jo][tx*8+4];
                ull vp[4] = {v0.x, v0.y, v1.x, v1.y};
                #pragma unroll
                for (int i=0;i<8;i++){
                    ull pd; PACK2(pd, pbuf[i][jo], pbuf[i][jo]);
                    #pragma unroll
                    for (int p=0;p<4;p++) FMA2(O2[i][p], pd, vp[p], O2[i][p]);
                }
            }
        }
    }

    // ---- epilogue ----
    const int bb = bh >> 4, hh = bh & 15;
    #pragma unroll
    for (int i=0;i<8;i++){
        float inv = 1.0f / lrow[i];
        int l = q0 + ty*8 + i;
        float o[8];
        #pragma unroll
        for (int p=0;p<4;p++){
            float lo, hi; UNPACK2(lo, hi, O2[i][p]);
            o[2*p] = lo*inv; o[2*p+1] = hi*inv;
        }
        float* op = &out[((size_t)bb*L + l)*DIMM + hh*DH + tx*8];
        *(float4*)&op[0] = make_float4(o[0],o[1],o[2],o[3]);
        *(float4*)&op[4] = make_float4(o[4],o[5],o[6],o[7]);
    }
}

// ---------------- launch ----------------
extern "C" void kernel_launch(void* const* d_in, const int* in_sizes, int n_in,
                              void* d_out, int out_size) {
    const float* X  = (const float*)d_in[0];
    const float* Wq = (const float*)d_in[1];
    const float* bq = (const float*)d_in[2];
    const float* Wv = (const float*)d_in[3];
    const float* bv = (const float*)d_in[4];
    const float* ha = (const float*)d_in[5];
    float* out = (float*)d_out;

    dim3 pg(DIMM/64, TOK/128, 2);
    proj_kernel<<<pg, 128>>>(X, Wq, bq, Wv, bv);

    init_maxn_kernel<<<1, 32>>>();
    hash1_kernel<<<(BH*L*32)/256, 256>>>(ha);
    hash2_kernel<<<(BH*L)/256, 256>>>(ha);

    cudaFuncSetAttribute(attn_kernel, cudaFuncAttributeMaxDynamicSharedMemorySize, ATTN_SM_BYTES);
    dim3 ag(L/AM, BH);
    attn_kernel<<<ag, 128, ATTN_SM_BYTES>>>(out);
}

// round 3
// speedup vs baseline: 1.8582x; 1.7929x over previous
#include <cuda_runtime.h>
#include <math.h>
#include <stdint.h>

#define B 2
#define L 2048
#define DIMM 1024
#define H 16
#define DH 64
#define BH (B*H)      // 32
#define TOK (B*L)     // 4096

typedef unsigned long long ull;

#define FMA2(d_, a_, b_, c_) asm("fma.rn.f32x2 %0, %1, %2, %3;" : "=l"(d_) : "l"(a_), "l"(b_), "l"(c_))
#define PACK2(d_, lo_, hi_)  asm("mov.b64 %0, {%1, %2};"        : "=l"(d_) : "f"(lo_), "f"(hi_))
#define UNPACK2(lo_, hi_, s_) asm("mov.b64 {%0, %1}, %2;"       : "=f"(lo_), "=f"(hi_) : "l"(s_))

// ---------------- scratch (static device globals; no allocs) ----------------
__device__ float g_qk[BH*L*DH];          // (b,h,l,d)
__device__ float g_v [BH*L*DH];          // (b,h,l,d)
__device__ float g_dot[BH*L];
__device__ float g_norm2[BH*L];
__device__ unsigned int g_maxn2[BH];
__device__ unsigned char g_hq[BH*L];
__device__ unsigned char g_hk[BH*L];

// ============ projection GEMM (fp32, unchanged from R2) ============
#define PBK 16

__global__ __launch_bounds__(128)
void proj_kernel(const float* __restrict__ X,
                 const float* __restrict__ Wq, const float* __restrict__ bq,
                 const float* __restrict__ Wv, const float* __restrict__ bv)
{
    __shared__ float Xt[PBK][132];
    __shared__ float Wt[PBK][68];

    const float* W    = blockIdx.z ? Wv : Wq;
    const float* bias = blockIdx.z ? bv : bq;
    float* out        = blockIdx.z ? g_v : g_qk;

    const int m0 = blockIdx.y * 128;
    const int n0 = blockIdx.x * 64;
    const int tid = threadIdx.x;
    const int tx = tid & 7, ty = tid >> 3;

    ull acc[8][4];
    #pragma unroll
    for (int i=0;i<8;i++)
        #pragma unroll
        for (int j=0;j<4;j++) acc[i][j] = 0ull;

    const int wn = tid >> 1;
    const int wk = (tid & 1) * 8;

    for (int kk = 0; kk < DIMM; kk += PBK) {
        __syncthreads();
        {
            const float* xp = &X[(size_t)(m0+tid)*DIMM + kk];
            #pragma unroll
            for (int c4 = 0; c4 < 4; c4++) {
                float4 a = *(const float4*)&xp[c4*4];
                Xt[c4*4+0][tid]=a.x; Xt[c4*4+1][tid]=a.y;
                Xt[c4*4+2][tid]=a.z; Xt[c4*4+3][tid]=a.w;
            }
        }
        {
            const float* wp = &W[(size_t)(n0+wn)*DIMM + kk + wk];
            #pragma unroll
            for (int c4 = 0; c4 < 2; c4++) {
                float4 a = *(const float4*)&wp[c4*4];
                Wt[wk+c4*4+0][wn]=a.x; Wt[wk+c4*4+1][wn]=a.y;
                Wt[wk+c4*4+2][wn]=a.z; Wt[wk+c4*4+3][wn]=a.w;
            }
        }
        __syncthreads();

        #pragma unroll
        for (int k = 0; k < PBK; k++) {
            float4 a0 = *(const float4*)&Xt[k][ty*8];
            float4 a1 = *(const float4*)&Xt[k][ty*8+4];
            ulonglong2 b0 = *(const ulonglong2*)&Wt[k][tx*8];
            ulonglong2 b1 = *(const ulonglong2*)&Wt[k][tx*8+4];
            ull bp[4] = {b0.x, b0.y, b1.x, b1.y};
            float av[8] = {a0.x,a0.y,a0.z,a0.w,a1.x,a1.y,a1.z,a1.w};
            #pragma unroll
            for (int i=0;i<8;i++){
                ull ad; PACK2(ad, av[i], av[i]);
                #pragma unroll
                for (int j=0;j<4;j++) FMA2(acc[i][j], ad, bp[j], acc[i][j]);
            }
        }
    }

    const int hh = n0 >> 6;
    #pragma unroll
    for (int i=0;i<8;i++){
        int m = m0 + ty*8 + i;
        int bb = m >> 11, ll = m & (L-1);
        float o[8];
        #pragma unroll
        for (int j=0;j<4;j++){
            float lo, hi; UNPACK2(lo, hi, acc[i][j]);
            o[2*j]   = lo + bias[n0 + tx*8 + 2*j];
            o[2*j+1] = hi + bias[n0 + tx*8 + 2*j+1];
        }
        float* op = &out[(((size_t)(bb*H + hh)*L + ll)*DH) + tx*8];
        *(float4*)&op[0] = make_float4(o[0],o[1],o[2],o[3]);
        *(float4*)&op[4] = make_float4(o[4],o[5],o[6],o[7]);
    }
}

// ---------------- hash pipeline (unchanged) ----------------
__global__ void init_maxn_kernel() {
    if (threadIdx.x < BH) g_maxn2[threadIdx.x] = 0u;
}

__global__ void hash1_kernel(const float* __restrict__ ha) {
    int gw = (blockIdx.x * blockDim.x + threadIdx.x) >> 5;
    int lane = threadIdx.x & 31;
    if (gw >= BH*L) return;
    const float* q = &g_qk[(size_t)gw * DH];
    float v0 = q[lane], v1 = q[lane+32];
    float dot = v0*ha[lane] + v1*ha[lane+32];
    float n2  = v0*v0 + v1*v1;
    #pragma unroll
    for (int o=16;o;o>>=1){
        dot += __shfl_xor_sync(0xffffffffu, dot, o);
        n2  += __shfl_xor_sync(0xffffffffu, n2,  o);
    }
    if (lane == 0) {
        g_dot[gw] = dot;
        g_norm2[gw] = n2;
        atomicMax(&g_maxn2[gw >> 11], __float_as_uint(n2));
    }
}

__global__ void hash2_kernel(const float* __restrict__ ha) {
    int t = blockIdx.x * blockDim.x + threadIdx.x;
    if (t >= BH*L) return;
    float dot = g_dot[t], n2 = g_norm2[t];
    float maxn = sqrtf(__uint_as_float(g_maxn2[t >> 11]));
    float s = 0.75f / fmaxf(maxn, 1e-12f);
    float nk2 = s*s*n2;
    float hkval = s*dot + (0.5f - nk2)*ha[DH] + (0.5f - nk2*nk2)*ha[DH+1];
    g_hq[t] = (dot   >= 0.0f) ? 1 : 0;
    g_hk[t] = (hkval >= 0.0f) ? 1 : 0;
}

// ============ tf32 tensor-core flash attention ============
// block: 256 threads (8 warps), Q-tile 128 rows, K-tile 64 keys.
// warp w owns q rows [w*16, w*16+16). mma.m16n8k8 tf32.

#define QS_STR 68
#define KS_STR 68
#define VS_STR 72
#define PS_STR 68

#define QS_OFF 0
#define KS_OFF (QS_OFF + 128*QS_STR)     // 8704
#define VS_OFF (KS_OFF + 64*KS_STR)      // 13056
#define PS_OFF (VS_OFF + 64*VS_STR)      // 17664
#define HK_OFF (PS_OFF + 128*PS_STR)     // 26368
#define ASM_WORDS (HK_OFF + 64)          // 26432
#define ASM_BYTES (ASM_WORDS*4)          // 105728

__device__ __forceinline__ uint32_t f2tf(float f){
    uint32_t r; asm("cvt.rna.tf32.f32 %0, %1;" : "=r"(r) : "f"(f)); return r;
}

__device__ __forceinline__ void mma_tf32(float c[4],
    uint32_t a0, uint32_t a1, uint32_t a2, uint32_t a3,
    uint32_t b0, uint32_t b1)
{
    asm("mma.sync.aligned.m16n8k8.row.col.f32.tf32.tf32.f32 "
        "{%0,%1,%2,%3}, {%4,%5,%6,%7}, {%8,%9}, {%0,%1,%2,%3};"
        : "+f"(c[0]), "+f"(c[1]), "+f"(c[2]), "+f"(c[3])
        : "r"(a0), "r"(a1), "r"(a2), "r"(a3), "r"(b0), "r"(b1));
}

__global__ __launch_bounds__(256, 2)
void attn_kernel(float* __restrict__ out) {
    extern __shared__ uint32_t sm[];
    uint32_t* Qs = sm + QS_OFF;
    uint32_t* Ks = sm + KS_OFF;
    uint32_t* Vs = sm + VS_OFF;
    uint32_t* Ps = sm + PS_OFF;
    float*   hkf = (float*)(sm + HK_OFF);

    const int bh = blockIdx.y;
    const int q0 = blockIdx.x * 128;
    const int tid = threadIdx.x;
    const int warp = tid >> 5;
    const int lane = tid & 31;
    const int gy = lane >> 2;          // 0..7
    const int gx = lane & 3;           // 0..3
    const int qr = warp * 16;          // warp's q-row base in tile

    // ---- fill Q tile (tf32-rounded) ----
    {
        int r = tid >> 1, c0 = (tid & 1) * 32;
        const float* qp = &g_qk[((size_t)bh*L + q0 + r)*DH + c0];
        #pragma unroll
        for (int c4 = 0; c4 < 8; c4++) {
            float4 a = *(const float4*)&qp[c4*4];
            uint4 u = make_uint4(f2tf(a.x), f2tf(a.y), f2tf(a.z), f2tf(a.w));
            *(uint4*)&Qs[r*QS_STR + c0 + c4*4] = u;
        }
    }

    // my 2 rows' hash bits as floats
    const float fq0 = (float)g_hq[(size_t)bh*L + q0 + qr + gy];
    const float fq1 = (float)g_hq[(size_t)bh*L + q0 + qr + gy + 8];

    float O[8][4];
    #pragma unroll
    for (int nt=0;nt<8;nt++)
        #pragma unroll
        for (int c=0;c<4;c++) O[nt][c] = 0.0f;
    float m0 = -INFINITY, m1 = -INFINITY, l0 = 0.0f, l1 = 0.0f;

    const int fr = tid >> 2;            // 0..63 row for K/V fill
    const int fc = (tid & 3) * 16;      // col chunk

    for (int k0 = 0; k0 < L; k0 += 64) {
        // prefetch K/V tile + hash bytes into registers (overlaps prev compute via sync wait)
        float4 kr[4], vr[4];
        {
            const float* kp = &g_qk[((size_t)bh*L + k0 + fr)*DH + fc];
            const float* vp = &g_v [((size_t)bh*L + k0 + fr)*DH + fc];
            #pragma unroll
            for (int c4=0;c4<4;c4++){ kr[c4] = *(const float4*)&kp[c4*4]; vr[c4] = *(const float4*)&vp[c4*4]; }
        }
        unsigned char hkb = 0;
        if (tid < 64) hkb = g_hk[(size_t)bh*L + k0 + tid];

        __syncthreads();   // prev-iter consumers of Ks/Vs done
        #pragma unroll
        for (int c4=0;c4<4;c4++){
            *(uint4*)&Ks[fr*KS_STR + fc + c4*4] =
                make_uint4(f2tf(kr[c4].x), f2tf(kr[c4].y), f2tf(kr[c4].z), f2tf(kr[c4].w));
            *(uint4*)&Vs[fr*VS_STR + fc + c4*4] =
                make_uint4(f2tf(vr[c4].x), f2tf(vr[c4].y), f2tf(vr[c4].z), f2tf(vr[c4].w));
        }
        if (tid < 64) hkf[tid] = (float)hkb;
        __syncthreads();

        // ---- S = Q @ K^T ----
        float S[8][4];
        #pragma unroll
        for (int nt=0;nt<8;nt++)
            #pragma unroll
            for (int c=0;c<4;c++) S[nt][c] = 0.0f;

        #pragma unroll
        for (int ks = 0; ks < 8; ks++) {
            uint32_t a0 = Qs[(qr+gy  )*QS_STR + ks*8 + gx];
            uint32_t a1 = Qs[(qr+gy+8)*QS_STR + ks*8 + gx];
            uint32_t a2 = Qs[(qr+gy  )*QS_STR + ks*8 + gx + 4];
            uint32_t a3 = Qs[(qr+gy+8)*QS_STR + ks*8 + gx + 4];
            #pragma unroll
            for (int nt = 0; nt < 8; nt++) {
                uint32_t b0 = Ks[(nt*8+gy)*KS_STR + ks*8 + gx];
                uint32_t b1 = Ks[(nt*8+gy)*KS_STR + ks*8 + gx + 4];
                mma_tf32(S[nt], a0, a1, a2, a3, b0, b1);
            }
        }

        // ---- mask + scale; tile row max ----
        float mx0 = -INFINITY, mx1 = -INFINITY;
        #pragma unroll
        for (int nt = 0; nt < 8; nt++) {
            float fk0 = hkf[nt*8 + 2*gx];
            float fk1 = hkf[nt*8 + 2*gx + 1];
            S[nt][0] = fmaf(S[nt][0], 0.125f, -1e4f*fabsf(fq0 - fk0));
            S[nt][1] = fmaf(S[nt][1], 0.125f, -1e4f*fabsf(fq0 - fk1));
            S[nt][2] = fmaf(S[nt][2], 0.125f, -1e4f*fabsf(fq1 - fk0));
            S[nt][3] = fmaf(S[nt][3], 0.125f, -1e4f*fabsf(fq1 - fk1));
            mx0 = fmaxf(mx0, fmaxf(S[nt][0], S[nt][1]));
            mx1 = fmaxf(mx1, fmaxf(S[nt][2], S[nt][3]));
        }
        #pragma unroll
        for (int o = 1; o <= 2; o <<= 1) {
            mx0 = fmaxf(mx0, __shfl_xor_sync(0xffffffffu, mx0, o));
            mx1 = fmaxf(mx1, __shfl_xor_sync(0xffffffffu, mx1, o));
        }
        float mn0 = fmaxf(m0, mx0), mn1 = fmaxf(m1, mx1);
        float cr0 = __expf(m0 - mn0), cr1 = __expf(m1 - mn1);
        m0 = mn0; m1 = mn1;

        // ---- exp, row sums, stage P (tf32) ----
        float s0 = 0.0f, s1 = 0.0f;
        #pragma unroll
        for (int nt = 0; nt < 8; nt++) {
            float p0 = __expf(S[nt][0] - mn0);
            float p1 = __expf(S[nt][1] - mn0);
            float p2 = __expf(S[nt][2] - mn1);
            float p3 = __expf(S[nt][3] - mn1);
            s0 += p0 + p1; s1 += p2 + p3;
            *(uint2*)&Ps[(qr+gy  )*PS_STR + nt*8 + 2*gx] = make_uint2(f2tf(p0), f2tf(p1));
            *(uint2*)&Ps[(qr+gy+8)*PS_STR + nt*8 + 2*gx] = make_uint2(f2tf(p2), f2tf(p3));
        }
        #pragma unroll
        for (int o = 1; o <= 2; o <<= 1) {
            s0 += __shfl_xor_sync(0xffffffffu, s0, o);
            s1 += __shfl_xor_sync(0xffffffffu, s1, o);
        }
        l0 = l0*cr0 + s0;
        l1 = l1*cr1 + s1;

        // rescale O
        #pragma unroll
        for (int nt = 0; nt < 8; nt++) {
            O[nt][0] *= cr0; O[nt][1] *= cr0;
            O[nt][2] *= cr1; O[nt][3] *= cr1;
        }
        __syncwarp();

        // ---- O += P @ V ----
        #pragma unroll
        for (int ks = 0; ks < 8; ks++) {
            uint32_t a0 = Ps[(qr+gy  )*PS_STR + ks*8 + gx];
            uint32_t a1 = Ps[(qr+gy+8)*PS_STR + ks*8 + gx];
            uint32_t a2 = Ps[(qr+gy  )*PS_STR + ks*8 + gx + 4];
            uint32_t a3 = Ps[(qr+gy+8)*PS_STR + ks*8 + gx + 4];
            #pragma unroll
            for (int nt = 0; nt < 8; nt++) {
                uint32_t b0 = Vs[(ks*8+gx  )*VS_STR + nt*8 + gy];
                uint32_t b1 = Vs[(ks*8+gx+4)*VS_STR + nt*8 + gy];
                mma_tf32(O[nt], a0, a1, a2, a3, b0, b1);
            }
        }
    }

    // ---- epilogue ----
    const int bb = bh >> 4, hh = bh & 15;
    const float inv0 = 1.0f / l0, inv1 = 1.0f / l1;
    const int l_0 = q0 + qr + gy, l_1 = l_0 + 8;
    float* o0 = &out[((size_t)bb*L + l_0)*DIMM + hh*DH];
    float* o1 = &out[((size_t)bb*L + l_1)*DIMM + hh*DH];
    #pragma unroll
    for (int nt = 0; nt < 8; nt++) {
        *(float2*)&o0[nt*8 + 2*gx] = make_float2(O[nt][0]*inv0, O[nt][1]*inv0);
        *(float2*)&o1[nt*8 + 2*gx] = make_float2(O[nt][2]*inv1, O[nt][3]*inv1);
    }
}

// ---------------- launch ----------------
extern "C" void kernel_launch(void* const* d_in, const int* in_sizes, int n_in,
                              void* d_out, int out_size) {
    const float* X  = (const float*)d_in[0];
    const float* Wq = (const float*)d_in[1];
    const float* bq = (const float*)d_in[2];
    const float* Wv = (const float*)d_in[3];
    const float* bv = (const float*)d_in[4];
    const float* ha = (const float*)d_in[5];
    float* out = (float*)d_out;

    dim3 pg(DIMM/64, TOK/128, 2);
    proj_kernel<<<pg, 128>>>(X, Wq, bq, Wv, bv);

    init_maxn_kernel<<<1, 32>>>();
    hash1_kernel<<<(BH*L*32)/256, 256>>>(ha);
    hash2_kernel<<<(BH*L)/256, 256>>>(ha);

    cudaFuncSetAttribute(attn_kernel, cudaFuncAttributeMaxDynamicSharedMemorySize, ASM_BYTES);
    dim3 ag(L/128, BH);
    attn_kernel<<<ag, 256, ASM_BYTES>>>(out);
}

// round 4
// speedup vs baseline: 2.2554x; 1.2137x over previous
#include <cuda_runtime.h>
#include <math.h>
#include <stdint.h>

#define B 2
#define L 2048
#define DIMM 1024
#define H 16
#define DH 64
#define BH (B*H)      // 32
#define TOK (B*L)     // 4096

// ---------------- scratch (static device globals; no allocs) ----------------
__device__ float g_qk[BH*L*DH];          // (b,h,l,d)
__device__ float g_v [BH*L*DH];          // (b,h,l,d)
__device__ float g_dot[BH*L];
__device__ float g_norm2[BH*L];
__device__ unsigned int g_maxn2[BH];
__device__ unsigned char g_hq[BH*L];
__device__ unsigned char g_hk[BH*L];

__device__ __forceinline__ uint32_t f2tf(float f){
    uint32_t r; asm("cvt.rna.tf32.f32 %0, %1;" : "=r"(r) : "f"(f)); return r;
}

__device__ __forceinline__ void mma_tf32(float c[4],
    uint32_t a0, uint32_t a1, uint32_t a2, uint32_t a3,
    uint32_t b0, uint32_t b1)
{
    asm("mma.sync.aligned.m16n8k8.row.col.f32.tf32.tf32.f32 "
        "{%0,%1,%2,%3}, {%4,%5,%6,%7}, {%8,%9}, {%0,%1,%2,%3};"
        : "+f"(c[0]), "+f"(c[1]), "+f"(c[2]), "+f"(c[3])
        : "r"(a0), "r"(a1), "r"(a2), "r"(a3), "r"(b0), "r"(b1));
}

// ============ tensor-core projection: out = X @ W^T + b -> (b,h,l,d) ============
// 256 thr / 8 warps. Tile M=128, N=64, Kc=32. THREE=1 -> 3xTF32 (fp32-accurate).
#define PSTR 36
#define XH_OFF 0
#define XL_OFF (128*PSTR)            // 4608
#define WH_OFF (2*128*PSTR)          // 9216
#define WL_OFF (WH_OFF + 64*PSTR)    // 11520
#define PROJ_SM_WORDS (WL_OFF + 64*PSTR)  // 13824
#define PROJ_SM_BYTES (PROJ_SM_WORDS*4)   // 55296

template<bool THREE>
__global__ __launch_bounds__(256, 2)
void proj_tc_kernel(const float* __restrict__ X,
                    const float* __restrict__ W,
                    const float* __restrict__ bias)
{
    extern __shared__ uint32_t psm[];
    uint32_t* XH = psm + XH_OFF;
    uint32_t* XL = psm + XL_OFF;
    uint32_t* WH = psm + WH_OFF;
    uint32_t* WL = psm + WL_OFF;

    float* out = THREE ? g_qk : g_v;

    const int m0 = blockIdx.y * 128;
    const int n0 = blockIdx.x * 64;
    const int tid = threadIdx.x;
    const int warp = tid >> 5;
    const int lane = tid & 31;
    const int gy = lane >> 2;          // 0..7
    const int gx = lane & 3;           // 0..3
    const int qr = warp * 16;

    const int fxr = tid >> 1;          // 0..127
    const int fxc = (tid & 1) * 16;
    const int fwr = tid >> 2;          // 0..63
    const int fwc = (tid & 3) * 8;

    float acc[8][4];
    #pragma unroll
    for (int nt=0;nt<8;nt++)
        #pragma unroll
        for (int c=0;c<4;c++) acc[nt][c] = 0.0f;

    const float* xp0 = &X[(size_t)(m0+fxr)*DIMM + fxc];
    const float* wp0 = &W[(size_t)(n0+fwr)*DIMM + fwc];

    for (int kk = 0; kk < DIMM; kk += 32) {
        // prefetch chunk to regs (overlaps previous compute until first sync)
        float4 xa[4], wa[2];
        #pragma unroll
        for (int j=0;j<4;j++) xa[j] = *(const float4*)&xp0[kk + j*4];
        #pragma unroll
        for (int j=0;j<2;j++) wa[j] = *(const float4*)&wp0[kk + j*4];

        __syncthreads();   // previous compute done reading smem

        #pragma unroll
        for (int j=0;j<4;j++){
            float v4[4] = {xa[j].x, xa[j].y, xa[j].z, xa[j].w};
            uint4 h, l;
            uint32_t* hp = &h.x; uint32_t* lp = &l.x;
            #pragma unroll
            for (int e=0;e<4;e++){
                uint32_t hi = f2tf(v4[e]);
                hp[e] = hi;
                if (THREE) lp[e] = f2tf(v4[e] - __uint_as_float(hi));
            }
            *(uint4*)&XH[fxr*PSTR + fxc + j*4] = h;
            if (THREE) *(uint4*)&XL[fxr*PSTR + fxc + j*4] = l;
        }
        #pragma unroll
        for (int j=0;j<2;j++){
            float v4[4] = {wa[j].x, wa[j].y, wa[j].z, wa[j].w};
            uint4 h, l;
            uint32_t* hp = &h.x; uint32_t* lp = &l.x;
            #pragma unroll
            for (int e=0;e<4;e++){
                uint32_t hi = f2tf(v4[e]);
                hp[e] = hi;
                if (THREE) lp[e] = f2tf(v4[e] - __uint_as_float(hi));
            }
            *(uint4*)&WH[fwr*PSTR + fwc + j*4] = h;
            if (THREE) *(uint4*)&WL[fwr*PSTR + fwc + j*4] = l;
        }
        __syncthreads();

        #pragma unroll
        for (int ks = 0; ks < 4; ks++) {
            uint32_t ah0 = XH[(qr+gy  )*PSTR + ks*8 + gx];
            uint32_t ah1 = XH[(qr+gy+8)*PSTR + ks*8 + gx];
            uint32_t ah2 = XH[(qr+gy  )*PSTR + ks*8 + gx + 4];
            uint32_t ah3 = XH[(qr+gy+8)*PSTR + ks*8 + gx + 4];
            uint32_t al0=0, al1=0, al2=0, al3=0;
            if (THREE) {
                al0 = XL[(qr+gy  )*PSTR + ks*8 + gx];
                al1 = XL[(qr+gy+8)*PSTR + ks*8 + gx];
                al2 = XL[(qr+gy  )*PSTR + ks*8 + gx + 4];
                al3 = XL[(qr+gy+8)*PSTR + ks*8 + gx + 4];
            }
            #pragma unroll
            for (int nt = 0; nt < 8; nt++) {
                uint32_t bh0 = WH[(nt*8+gy)*PSTR + ks*8 + gx];
                uint32_t bh1 = WH[(nt*8+gy)*PSTR + ks*8 + gx + 4];
                if (THREE) {
                    uint32_t bl0 = WL[(nt*8+gy)*PSTR + ks*8 + gx];
                    uint32_t bl1 = WL[(nt*8+gy)*PSTR + ks*8 + gx + 4];
                    mma_tf32(acc[nt], ah0, ah1, ah2, ah3, bl0, bl1);
                    mma_tf32(acc[nt], al0, al1, al2, al3, bh0, bh1);
                }
                mma_tf32(acc[nt], ah0, ah1, ah2, ah3, bh0, bh1);
            }
        }
    }

    // epilogue: rows m0+qr+gy(+8), cols n0 + nt*8 + 2gx(+1); one head per block-n
    const int hh = blockIdx.x;   // n0>>6
    const int m_0 = m0 + qr + gy;
    const int m_1 = m_0 + 8;
    const int b0_ = m_0 >> 11, l0_ = m_0 & (L-1);
    const int b1_ = m_1 >> 11, l1_ = m_1 & (L-1);
    float* o0 = &out[(((size_t)(b0_*H + hh)*L + l0_)*DH)];
    float* o1 = &out[(((size_t)(b1_*H + hh)*L + l1_)*DH)];
    #pragma unroll
    for (int nt = 0; nt < 8; nt++) {
        float bs0 = bias[hh*64 + nt*8 + 2*gx];
        float bs1 = bias[hh*64 + nt*8 + 2*gx + 1];
        *(float2*)&o0[nt*8 + 2*gx] = make_float2(acc[nt][0] + bs0, acc[nt][1] + bs1);
        *(float2*)&o1[nt*8 + 2*gx] = make_float2(acc[nt][2] + bs0, acc[nt][3] + bs1);
    }
}

// ---------------- hash pipeline (unchanged) ----------------
__global__ void init_maxn_kernel() {
    if (threadIdx.x < BH) g_maxn2[threadIdx.x] = 0u;
}

__global__ void hash1_kernel(const float* __restrict__ ha) {
    int gw = (blockIdx.x * blockDim.x + threadIdx.x) >> 5;
    int lane = threadIdx.x & 31;
    if (gw >= BH*L) return;
    const float* q = &g_qk[(size_t)gw * DH];
    float v0 = q[lane], v1 = q[lane+32];
    float dot = v0*ha[lane] + v1*ha[lane+32];
    float n2  = v0*v0 + v1*v1;
    #pragma unroll
    for (int o=16;o;o>>=1){
        dot += __shfl_xor_sync(0xffffffffu, dot, o);
        n2  += __shfl_xor_sync(0xffffffffu, n2,  o);
    }
    if (lane == 0) {
        g_dot[gw] = dot;
        g_norm2[gw] = n2;
        atomicMax(&g_maxn2[gw >> 11], __float_as_uint(n2));
    }
}

__global__ void hash2_kernel(const float* __restrict__ ha) {
    int t = blockIdx.x * blockDim.x + threadIdx.x;
    if (t >= BH*L) return;
    float dot = g_dot[t], n2 = g_norm2[t];
    float maxn = sqrtf(__uint_as_float(g_maxn2[t >> 11]));
    float s = 0.75f / fmaxf(maxn, 1e-12f);
    float nk2 = s*s*n2;
    float hkval = s*dot + (0.5f - nk2)*ha[DH] + (0.5f - nk2*nk2)*ha[DH+1];
    g_hq[t] = (dot   >= 0.0f) ? 1 : 0;
    g_hk[t] = (hkval >= 0.0f) ? 1 : 0;
}

// ============ tf32 tensor-core flash attention (unchanged from R3) ============
#define QS_STR 68
#define KS_STR 68
#define VS_STR 72
#define PS_STR 68

#define QS_OFF 0
#define KS_OFF (QS_OFF + 128*QS_STR)
#define VS_OFF (KS_OFF + 64*KS_STR)
#define PS_OFF (VS_OFF + 64*VS_STR)
#define HK_OFF (PS_OFF + 128*PS_STR)
#define ASM_WORDS (HK_OFF + 64)
#define ASM_BYTES (ASM_WORDS*4)

__global__ __launch_bounds__(256, 2)
void attn_kernel(float* __restrict__ out) {
    extern __shared__ uint32_t sm[];
    uint32_t* Qs = sm + QS_OFF;
    uint32_t* Ks = sm + KS_OFF;
    uint32_t* Vs = sm + VS_OFF;
    uint32_t* Ps = sm + PS_OFF;
    float*   hkf = (float*)(sm + HK_OFF);

    const int bh = blockIdx.y;
    const int q0 = blockIdx.x * 128;
    const int tid = threadIdx.x;
    const int warp = tid >> 5;
    const int lane = tid & 31;
    const int gy = lane >> 2;
    const int gx = lane & 3;
    const int qr = warp * 16;

    {
        int r = tid >> 1, c0 = (tid & 1) * 32;
        const float* qp = &g_qk[((size_t)bh*L + q0 + r)*DH + c0];
        #pragma unroll
        for (int c4 = 0; c4 < 8; c4++) {
            float4 a = *(const float4*)&qp[c4*4];
            uint4 u = make_uint4(f2tf(a.x), f2tf(a.y), f2tf(a.z), f2tf(a.w));
            *(uint4*)&Qs[r*QS_STR + c0 + c4*4] = u;
        }
    }

    const float fq0 = (float)g_hq[(size_t)bh*L + q0 + qr + gy];
    const float fq1 = (float)g_hq[(size_t)bh*L + q0 + qr + gy + 8];

    float O[8][4];
    #pragma unroll
    for (int nt=0;nt<8;nt++)
        #pragma unroll
        for (int c=0;c<4;c++) O[nt][c] = 0.0f;
    float m0 = -INFINITY, m1 = -INFINITY, l0 = 0.0f, l1 = 0.0f;

    const int fr = tid >> 2;
    const int fc = (tid & 3) * 16;

    for (int k0 = 0; k0 < L; k0 += 64) {
        float4 kr[4], vr[4];
        {
            const float* kp = &g_qk[((size_t)bh*L + k0 + fr)*DH + fc];
            const float* vp = &g_v [((size_t)bh*L + k0 + fr)*DH + fc];
            #pragma unroll
            for (int c4=0;c4<4;c4++){ kr[c4] = *(const float4*)&kp[c4*4]; vr[c4] = *(const float4*)&vp[c4*4]; }
        }
        unsigned char hkb = 0;
        if (tid < 64) hkb = g_hk[(size_t)bh*L + k0 + tid];

        __syncthreads();
        #pragma unroll
        for (int c4=0;c4<4;c4++){
            *(uint4*)&Ks[fr*KS_STR + fc + c4*4] =
                make_uint4(f2tf(kr[c4].x), f2tf(kr[c4].y), f2tf(kr[c4].z), f2tf(kr[c4].w));
            *(uint4*)&Vs[fr*VS_STR + fc + c4*4] =
                make_uint4(f2tf(vr[c4].x), f2tf(vr[c4].y), f2tf(vr[c4].z), f2tf(vr[c4].w));
        }
        if (tid < 64) hkf[tid] = (float)hkb;
        __syncthreads();

        float S[8][4];
        #pragma unroll
        for (int nt=0;nt<8;nt++)
            #pragma unroll
            for (int c=0;c<4;c++) S[nt][c] = 0.0f;

        #pragma unroll
        for (int ks = 0; ks < 8; ks++) {
            uint32_t a0 = Qs[(qr+gy  )*QS_STR + ks*8 + gx];
            uint32_t a1 = Qs[(qr+gy+8)*QS_STR + ks*8 + gx];
            uint32_t a2 = Qs[(qr+gy  )*QS_STR + ks*8 + gx + 4];
            uint32_t a3 = Qs[(qr+gy+8)*QS_STR + ks*8 + gx + 4];
            #pragma unroll
            for (int nt = 0; nt < 8; nt++) {
                uint32_t b0 = Ks[(nt*8+gy)*KS_STR + ks*8 + gx];
                uint32_t b1 = Ks[(nt*8+gy)*KS_STR + ks*8 + gx + 4];
                mma_tf32(S[nt], a0, a1, a2, a3, b0, b1);
            }
        }

        float mx0 = -INFINITY, mx1 = -INFINITY;
        #pragma unroll
        for (int nt = 0; nt < 8; nt++) {
            float fk0 = hkf[nt*8 + 2*gx];
            float fk1 = hkf[nt*8 + 2*gx + 1];
            S[nt][0] = fmaf(S[nt][0], 0.125f, -1e4f*fabsf(fq0 - fk0));
            S[nt][1] = fmaf(S[nt][1], 0.125f, -1e4f*fabsf(fq0 - fk1));
            S[nt][2] = fmaf(S[nt][2], 0.125f, -1e4f*fabsf(fq1 - fk0));
            S[nt][3] = fmaf(S[nt][3], 0.125f, -1e4f*fabsf(fq1 - fk1));
            mx0 = fmaxf(mx0, fmaxf(S[nt][0], S[nt][1]));
            mx1 = fmaxf(mx1, fmaxf(S[nt][2], S[nt][3]));
        }
        #pragma unroll
        for (int o = 1; o <= 2; o <<= 1) {
            mx0 = fmaxf(mx0, __shfl_xor_sync(0xffffffffu, mx0, o));
            mx1 = fmaxf(mx1, __shfl_xor_sync(0xffffffffu, mx1, o));
        }
        float mn0 = fmaxf(m0, mx0), mn1 = fmaxf(m1, mx1);
        float cr0 = __expf(m0 - mn0), cr1 = __expf(m1 - mn1);
        m0 = mn0; m1 = mn1;

        float s0 = 0.0f, s1 = 0.0f;
        #pragma unroll
        for (int nt = 0; nt < 8; nt++) {
            float p0 = __expf(S[nt][0] - mn0);
            float p1 = __expf(S[nt][1] - mn0);
            float p2 = __expf(S[nt][2] - mn1);
            float p3 = __expf(S[nt][3] - mn1);
            s0 += p0 + p1; s1 += p2 + p3;
            *(uint2*)&Ps[(qr+gy  )*PS_STR + nt*8 + 2*gx] = make_uint2(f2tf(p0), f2tf(p1));
            *(uint2*)&Ps[(qr+gy+8)*PS_STR + nt*8 + 2*gx] = make_uint2(f2tf(p2), f2tf(p3));
        }
        #pragma unroll
        for (int o = 1; o <= 2; o <<= 1) {
            s0 += __shfl_xor_sync(0xffffffffu, s0, o);
            s1 += __shfl_xor_sync(0xffffffffu, s1, o);
        }
        l0 = l0*cr0 + s0;
        l1 = l1*cr1 + s1;

        #pragma unroll
        for (int nt = 0; nt < 8; nt++) {
            O[nt][0] *= cr0; O[nt][1] *= cr0;
            O[nt][2] *= cr1; O[nt][3] *= cr1;
        }
        __syncwarp();

        #pragma unroll
        for (int ks = 0; ks < 8; ks++) {
            uint32_t a0 = Ps[(qr+gy  )*PS_STR + ks*8 + gx];
            uint32_t a1 = Ps[(qr+gy+8)*PS_STR + ks*8 + gx];
            uint32_t a2 = Ps[(qr+gy  )*PS_STR + ks*8 + gx + 4];
            uint32_t a3 = Ps[(qr+gy+8)*PS_STR + ks*8 + gx + 4];
            #pragma unroll
            for (int nt = 0; nt < 8; nt++) {
                uint32_t b0 = Vs[(ks*8+gx  )*VS_STR + nt*8 + gy];
                uint32_t b1 = Vs[(ks*8+gx+4)*VS_STR + nt*8 + gy];
                mma_tf32(O[nt], a0, a1, a2, a3, b0, b1);
            }
        }
    }

    const int bb = bh >> 4, hh = bh & 15;
    const float inv0 = 1.0f / l0, inv1 = 1.0f / l1;
    const int l_0 = q0 + qr + gy, l_1 = l_0 + 8;
    float* o0 = &out[((size_t)bb*L + l_0)*DIMM + hh*DH];
    float* o1 = &out[((size_t)bb*L + l_1)*DIMM + hh*DH];
    #pragma unroll
    for (int nt = 0; nt < 8; nt++) {
        *(float2*)&o0[nt*8 + 2*gx] = make_float2(O[nt][0]*inv0, O[nt][1]*inv0);
        *(float2*)&o1[nt*8 + 2*gx] = make_float2(O[nt][2]*inv1, O[nt][3]*inv1);
    }
}

// ---------------- launch ----------------
extern "C" void kernel_launch(void* const* d_in, const int* in_sizes, int n_in,
                              void* d_out, int out_size) {
    const float* X  = (const float*)d_in[0];
    const float* Wq = (const float*)d_in[1];
    const float* bq = (const float*)d_in[2];
    const float* Wv = (const float*)d_in[3];
    const float* bv = (const float*)d_in[4];
    const float* ha = (const float*)d_in[5];
    float* out = (float*)d_out;

    cudaFuncSetAttribute(proj_tc_kernel<true>,  cudaFuncAttributeMaxDynamicSharedMemorySize, PROJ_SM_BYTES);
    cudaFuncSetAttribute(proj_tc_kernel<false>, cudaFuncAttributeMaxDynamicSharedMemorySize, PROJ_SM_BYTES);

    dim3 pg(DIMM/64, TOK/128);
    proj_tc_kernel<true ><<<pg, 256, PROJ_SM_BYTES>>>(X, Wq, bq);   // qk (3xTF32)
    proj_tc_kernel<false><<<pg, 256, PROJ_SM_BYTES>>>(X, Wv, bv);   // v  (1xTF32)

    init_maxn_kernel<<<1, 32>>>();
    hash1_kernel<<<(BH*L*32)/256, 256>>>(ha);
    hash2_kernel<<<(BH*L)/256, 256>>>(ha);

    cudaFuncSetAttribute(attn_kernel, cudaFuncAttributeMaxDynamicSharedMemorySize, ASM_BYTES);
    dim3 ag(L/128, BH);
    attn_kernel<<<ag, 256, ASM_BYTES>>>(out);
}

// round 5
// speedup vs baseline: 2.7590x; 1.2233x over previous
#include <cuda_runtime.h>
#include <cuda_fp16.h>
#include <math.h>
#include <stdint.h>

#define B 2
#define L 2048
#define DIMM 1024
#define H 16
#define DH 64
#define BH (B*H)      // 32
#define TOK (B*L)     // 4096

// ---------------- scratch ----------------
__device__ float g_qk[BH*L*DH];
__device__ float g_v [BH*L*DH];
__device__ float g_dot[BH*L];
__device__ float g_norm2[BH*L];
__device__ unsigned int g_maxn2[BH];
__device__ unsigned char g_hq[BH*L];
__device__ unsigned char g_hk[BH*L];

__device__ __forceinline__ uint32_t f2tf(float f){
    uint32_t r; asm("cvt.rna.tf32.f32 %0, %1;" : "=r"(r) : "f"(f)); return r;
}
__device__ __forceinline__ uint32_t f22h2(float a, float b){
    __half2 h = __floats2half2_rn(a, b);
    return *(uint32_t*)&h;
}

__device__ __forceinline__ void mma_tf32(float c[4],
    uint32_t a0, uint32_t a1, uint32_t a2, uint32_t a3,
    uint32_t b0, uint32_t b1)
{
    asm("mma.sync.aligned.m16n8k8.row.col.f32.tf32.tf32.f32 "
        "{%0,%1,%2,%3}, {%4,%5,%6,%7}, {%8,%9}, {%0,%1,%2,%3};"
        : "+f"(c[0]), "+f"(c[1]), "+f"(c[2]), "+f"(c[3])
        : "r"(a0), "r"(a1), "r"(a2), "r"(a3), "r"(b0), "r"(b1));
}
__device__ __forceinline__ void mma_f16(float c[4],
    uint32_t a0, uint32_t a1, uint32_t a2, uint32_t a3,
    uint32_t b0, uint32_t b1)
{
    asm("mma.sync.aligned.m16n8k16.row.col.f32.f16.f16.f32 "
        "{%0,%1,%2,%3}, {%4,%5,%6,%7}, {%8,%9}, {%0,%1,%2,%3};"
        : "+f"(c[0]), "+f"(c[1]), "+f"(c[2]), "+f"(c[3])
        : "r"(a0), "r"(a1), "r"(a2), "r"(a3), "r"(b0), "r"(b1));
}

// ============ tensor-core projection (tile M=128, N=64=one head, Kc=32) ============
// THREE=1: 3xTF32 qk projection with FUSED hash stage-1 in epilogue.
#define PSTR 36
#define XH_OFF 0
#define XL_OFF (128*PSTR)
#define WH_OFF (2*128*PSTR)
#define WL_OFF (WH_OFF + 64*PSTR)
#define PROJ_SM_WORDS (WL_OFF + 64*PSTR)
#define PROJ_SM_BYTES (PROJ_SM_WORDS*4)

template<bool THREE>
__global__ __launch_bounds__(256, 2)
void proj_tc_kernel(const float* __restrict__ X,
                    const float* __restrict__ W,
                    const float* __restrict__ bias,
                    const float* __restrict__ ha)
{
    extern __shared__ uint32_t psm[];
    uint32_t* XH = psm + XH_OFF;
    uint32_t* XL = psm + XL_OFF;
    uint32_t* WH = psm + WH_OFF;
    uint32_t* WL = psm + WL_OFF;

    float* out = THREE ? g_qk : g_v;

    const int m0 = blockIdx.y * 128;
    const int n0 = blockIdx.x * 64;
    const int tid = threadIdx.x;
    const int warp = tid >> 5;
    const int lane = tid & 31;
    const int gy = lane >> 2;
    const int gx = lane & 3;
    const int qr = warp * 16;

    const int fxr = tid >> 1;
    const int fxc = (tid & 1) * 16;
    const int fwr = tid >> 2;
    const int fwc = (tid & 3) * 8;

    float acc[8][4];
    #pragma unroll
    for (int nt=0;nt<8;nt++)
        #pragma unroll
        for (int c=0;c<4;c++) acc[nt][c] = 0.0f;

    const float* xp0 = &X[(size_t)(m0+fxr)*DIMM + fxc];
    const float* wp0 = &W[(size_t)(n0+fwr)*DIMM + fwc];

    for (int kk = 0; kk < DIMM; kk += 32) {
        float4 xa[4], wa[2];
        #pragma unroll
        for (int j=0;j<4;j++) xa[j] = *(const float4*)&xp0[kk + j*4];
        #pragma unroll
        for (int j=0;j<2;j++) wa[j] = *(const float4*)&wp0[kk + j*4];

        __syncthreads();

        #pragma unroll
        for (int j=0;j<4;j++){
            float v4[4] = {xa[j].x, xa[j].y, xa[j].z, xa[j].w};
            uint4 h, l;
            uint32_t* hp = &h.x; uint32_t* lp = &l.x;
            #pragma unroll
            for (int e=0;e<4;e++){
                uint32_t hi = f2tf(v4[e]);
                hp[e] = hi;
                if (THREE) lp[e] = f2tf(v4[e] - __uint_as_float(hi));
            }
            *(uint4*)&XH[fxr*PSTR + fxc + j*4] = h;
            if (THREE) *(uint4*)&XL[fxr*PSTR + fxc + j*4] = l;
        }
        #pragma unroll
        for (int j=0;j<2;j++){
            float v4[4] = {wa[j].x, wa[j].y, wa[j].z, wa[j].w};
            uint4 h, l;
            uint32_t* hp = &h.x; uint32_t* lp = &l.x;
            #pragma unroll
            for (int e=0;e<4;e++){
                uint32_t hi = f2tf(v4[e]);
                hp[e] = hi;
                if (THREE) lp[e] = f2tf(v4[e] - __uint_as_float(hi));
            }
            *(uint4*)&WH[fwr*PSTR + fwc + j*4] = h;
            if (THREE) *(uint4*)&WL[fwr*PSTR + fwc + j*4] = l;
        }
        __syncthreads();

        #pragma unroll
        for (int ks = 0; ks < 4; ks++) {
            uint32_t ah0 = XH[(qr+gy  )*PSTR + ks*8 + gx];
            uint32_t ah1 = XH[(qr+gy+8)*PSTR + ks*8 + gx];
            uint32_t ah2 = XH[(qr+gy  )*PSTR + ks*8 + gx + 4];
            uint32_t ah3 = XH[(qr+gy+8)*PSTR + ks*8 + gx + 4];
            uint32_t al0=0, al1=0, al2=0, al3=0;
            if (THREE) {
                al0 = XL[(qr+gy  )*PSTR + ks*8 + gx];
                al1 = XL[(qr+gy+8)*PSTR + ks*8 + gx];
                al2 = XL[(qr+gy  )*PSTR + ks*8 + gx + 4];
                al3 = XL[(qr+gy+8)*PSTR + ks*8 + gx + 4];
            }
            #pragma unroll
            for (int nt = 0; nt < 8; nt++) {
                uint32_t bh0 = WH[(nt*8+gy)*PSTR + ks*8 + gx];
                uint32_t bh1 = WH[(nt*8+gy)*PSTR + ks*8 + gx + 4];
                if (THREE) {
                    uint32_t bl0 = WL[(nt*8+gy)*PSTR + ks*8 + gx];
                    uint32_t bl1 = WL[(nt*8+gy)*PSTR + ks*8 + gx + 4];
                    mma_tf32(acc[nt], ah0, ah1, ah2, ah3, bl0, bl1);
                    mma_tf32(acc[nt], al0, al1, al2, al3, bh0, bh1);
                }
                mma_tf32(acc[nt], ah0, ah1, ah2, ah3, bh0, bh1);
            }
        }
    }

    const int hh = blockIdx.x;
    const int m_0 = m0 + qr + gy;
    const int m_1 = m_0 + 8;
    const int b0_ = m_0 >> 11, l0_ = m_0 & (L-1);
    const int b1_ = m_1 >> 11, l1_ = m_1 & (L-1);
    float* o0 = &out[(((size_t)(b0_*H + hh)*L + l0_)*DH)];
    float* o1 = &out[(((size_t)(b1_*H + hh)*L + l1_)*DH)];

    float dot0 = 0.f, n20 = 0.f, dot1 = 0.f, n21 = 0.f;
    #pragma unroll
    for (int nt = 0; nt < 8; nt++) {
        float bs0 = bias[hh*64 + nt*8 + 2*gx];
        float bs1 = bias[hh*64 + nt*8 + 2*gx + 1];
        float v00 = acc[nt][0] + bs0, v01 = acc[nt][1] + bs1;
        float v10 = acc[nt][2] + bs0, v11 = acc[nt][3] + bs1;
        *(float2*)&o0[nt*8 + 2*gx] = make_float2(v00, v01);
        *(float2*)&o1[nt*8 + 2*gx] = make_float2(v10, v11);
        if (THREE) {
            float a0 = ha[nt*8 + 2*gx], a1 = ha[nt*8 + 2*gx + 1];
            dot0 = fmaf(v00, a0, fmaf(v01, a1, dot0));
            dot1 = fmaf(v10, a0, fmaf(v11, a1, dot1));
            n20  = fmaf(v00, v00, fmaf(v01, v01, n20));
            n21  = fmaf(v10, v10, fmaf(v11, v11, n21));
        }
    }
    if (THREE) {
        #pragma unroll
        for (int o = 1; o <= 2; o <<= 1) {
            dot0 += __shfl_xor_sync(0xffffffffu, dot0, o);
            dot1 += __shfl_xor_sync(0xffffffffu, dot1, o);
            n20  += __shfl_xor_sync(0xffffffffu, n20, o);
            n21  += __shfl_xor_sync(0xffffffffu, n21, o);
        }
        if (gx == 0) {
            size_t gw0 = (size_t)(b0_*H + hh)*L + l0_;
            size_t gw1 = (size_t)(b1_*H + hh)*L + l1_;
            g_dot[gw0] = dot0; g_norm2[gw0] = n20;
            g_dot[gw1] = dot1; g_norm2[gw1] = n21;
            atomicMax(&g_maxn2[b0_*H + hh], __float_as_uint(n20));
            atomicMax(&g_maxn2[b1_*H + hh], __float_as_uint(n21));
        }
    }
}

// ---------------- hash ----------------
__global__ void init_maxn_kernel() {
    if (threadIdx.x < BH) g_maxn2[threadIdx.x] = 0u;
}

__global__ void hash2_kernel(const float* __restrict__ ha) {
    int t = blockIdx.x * blockDim.x + threadIdx.x;
    if (t >= BH*L) return;
    float dot = g_dot[t], n2 = g_norm2[t];
    float maxn = sqrtf(__uint_as_float(g_maxn2[t >> 11]));
    float s = 0.75f / fmaxf(maxn, 1e-12f);
    float nk2 = s*s*n2;
    float hkval = s*dot + (0.5f - nk2)*ha[DH] + (0.5f - nk2*nk2)*ha[DH+1];
    g_hq[t] = (dot   >= 0.0f) ? 1 : 0;
    g_hk[t] = (hkval >= 0.0f) ? 1 : 0;
}

// ============ fp16 tensor-core flash attention ============
// 256 thr / 8 warps, Q-tile 128, K-tile 64, mma.m16n8k16.f16, fp32 softmax/accum.
#define HSTR 72   // halves per row (64 + 8 pad) -> 36 words, conflict-free frags

#define QS_OFF 0
#define KS_OFF (128*HSTR)            // 9216
#define VT_OFF (KS_OFF + 64*HSTR)    // 13824
#define PS_OFF (VT_OFF + 64*HSTR)    // 18432
#define HK_OFF (PS_OFF + 128*HSTR)   // 27648 (half units; 4B aligned)
#define ASM_HALVES (HK_OFF + 128)
#define ASM_BYTES (ASM_HALVES*2)     // 55552

__global__ __launch_bounds__(256, 2)
void attn_kernel(float* __restrict__ out) {
    extern __shared__ __half smh[];
    __half* Qs = smh + QS_OFF;
    __half* Ks = smh + KS_OFF;
    __half* Vt = smh + VT_OFF;
    __half* Ps = smh + PS_OFF;
    float* hkf = (float*)(smh + HK_OFF);

    const int bh = blockIdx.y;
    const int q0 = blockIdx.x * 128;
    const int tid = threadIdx.x;
    const int warp = tid >> 5;
    const int lane = tid & 31;
    const int gy = lane >> 2;
    const int gx = lane & 3;
    const int qr = warp * 16;

    // ---- Q fill (fp16) ----
    {
        int r = tid >> 1, c0 = (tid & 1) * 32;
        const float* qp = &g_qk[((size_t)bh*L + q0 + r)*DH + c0];
        #pragma unroll
        for (int c4 = 0; c4 < 8; c4++) {
            float4 a = *(const float4*)&qp[c4*4];
            *(uint2*)&Qs[r*HSTR + c0 + c4*4] =
                make_uint2(f22h2(a.x, a.y), f22h2(a.z, a.w));
        }
    }

    const float fq0 = (float)g_hq[(size_t)bh*L + q0 + qr + gy];
    const float fq1 = (float)g_hq[(size_t)bh*L + q0 + qr + gy + 8];

    float O[8][4];
    #pragma unroll
    for (int nt=0;nt<8;nt++)
        #pragma unroll
        for (int c=0;c<4;c++) O[nt][c] = 0.0f;
    float m0 = -INFINITY, m1 = -INFINITY, l0 = 0.0f, l1 = 0.0f;

    const int fr = tid >> 2;           // K fill row 0..63
    const int fc = (tid & 3) * 16;
    const int vd0 = warp * 8;          // V^T fill: this warp's 8 d-rows

    for (int k0 = 0; k0 < L; k0 += 64) {
        // prefetch K (natural) and V (2 rows for transpose) into regs
        float4 kr[4];
        {
            const float* kp = &g_qk[((size_t)bh*L + k0 + fr)*DH + fc];
            #pragma unroll
            for (int c4=0;c4<4;c4++) kr[c4] = *(const float4*)&kp[c4*4];
        }
        float4 va0, va1, vb0, vb1;
        {
            const float* vp0 = &g_v[((size_t)bh*L + k0 + 2*lane)*DH + vd0];
            va0 = *(const float4*)&vp0[0];
            va1 = *(const float4*)&vp0[4];
            vb0 = *(const float4*)&vp0[DH];
            vb1 = *(const float4*)&vp0[DH+4];
        }
        unsigned char hkb = 0;
        if (tid < 64) hkb = g_hk[(size_t)bh*L + k0 + tid];

        __syncthreads();
        #pragma unroll
        for (int c4=0;c4<4;c4++)
            *(uint2*)&Ks[fr*HSTR + fc + c4*4] =
                make_uint2(f22h2(((const float*)&kr[c4])[0], ((const float*)&kr[c4])[1]),
                           f22h2(((const float*)&kr[c4])[2], ((const float*)&kr[c4])[3]));
        {
            const float* a0p = (const float*)&va0; const float* a1p = (const float*)&va1;
            const float* b0p = (const float*)&vb0; const float* b1p = (const float*)&vb1;
            #pragma unroll
            for (int e=0;e<4;e++){
                *(uint32_t*)&Vt[(vd0+e  )*HSTR + 2*lane] = f22h2(a0p[e], b0p[e]);
                *(uint32_t*)&Vt[(vd0+e+4)*HSTR + 2*lane] = f22h2(a1p[e], b1p[e]);
            }
        }
        if (tid < 64) hkf[tid] = (float)hkb;
        __syncthreads();

        // ---- S = Q @ K^T ----
        float S[8][4];
        #pragma unroll
        for (int nt=0;nt<8;nt++)
            #pragma unroll
            for (int c=0;c<4;c++) S[nt][c] = 0.0f;

        #pragma unroll
        for (int ks = 0; ks < 4; ks++) {
            uint32_t a0 = *(uint32_t*)&Qs[(qr+gy  )*HSTR + ks*16 + 2*gx];
            uint32_t a1 = *(uint32_t*)&Qs[(qr+gy+8)*HSTR + ks*16 + 2*gx];
            uint32_t a2 = *(uint32_t*)&Qs[(qr+gy  )*HSTR + ks*16 + 2*gx + 8];
            uint32_t a3 = *(uint32_t*)&Qs[(qr+gy+8)*HSTR + ks*16 + 2*gx + 8];
            #pragma unroll
            for (int nt = 0; nt < 8; nt++) {
                uint32_t b0 = *(uint32_t*)&Ks[(nt*8+gy)*HSTR + ks*16 + 2*gx];
                uint32_t b1 = *(uint32_t*)&Ks[(nt*8+gy)*HSTR + ks*16 + 2*gx + 8];
                mma_f16(S[nt], a0, a1, a2, a3, b0, b1);
            }
        }

        // ---- mask + scale; row max ----
        float mx0 = -INFINITY, mx1 = -INFINITY;
        #pragma unroll
        for (int nt = 0; nt < 8; nt++) {
            float fk0 = hkf[nt*8 + 2*gx];
            float fk1 = hkf[nt*8 + 2*gx + 1];
            S[nt][0] = fmaf(S[nt][0], 0.125f, -1e4f*fabsf(fq0 - fk0));
            S[nt][1] = fmaf(S[nt][1], 0.125f, -1e4f*fabsf(fq0 - fk1));
            S[nt][2] = fmaf(S[nt][2], 0.125f, -1e4f*fabsf(fq1 - fk0));
            S[nt][3] = fmaf(S[nt][3], 0.125f, -1e4f*fabsf(fq1 - fk1));
            mx0 = fmaxf(mx0, fmaxf(S[nt][0], S[nt][1]));
            mx1 = fmaxf(mx1, fmaxf(S[nt][2], S[nt][3]));
        }
        #pragma unroll
        for (int o = 1; o <= 2; o <<= 1) {
            mx0 = fmaxf(mx0, __shfl_xor_sync(0xffffffffu, mx0, o));
            mx1 = fmaxf(mx1, __shfl_xor_sync(0xffffffffu, mx1, o));
        }
        float mn0 = fmaxf(m0, mx0), mn1 = fmaxf(m1, mx1);
        float cr0 = __expf(m0 - mn0), cr1 = __expf(m1 - mn1);
        m0 = mn0; m1 = mn1;

        // ---- exp, row sums, stage P (fp16) ----
        float s0 = 0.0f, s1 = 0.0f;
        #pragma unroll
        for (int nt = 0; nt < 8; nt++) {
            float p0 = __expf(S[nt][0] - mn0);
            float p1 = __expf(S[nt][1] - mn0);
            float p2 = __expf(S[nt][2] - mn1);
            float p3 = __expf(S[nt][3] - mn1);
            s0 += p0 + p1; s1 += p2 + p3;
            *(uint32_t*)&Ps[(qr+gy  )*HSTR + nt*8 + 2*gx] = f22h2(p0, p1);
            *(uint32_t*)&Ps[(qr+gy+8)*HSTR + nt*8 + 2*gx] = f22h2(p2, p3);
        }
        #pragma unroll
        for (int o = 1; o <= 2; o <<= 1) {
            s0 += __shfl_xor_sync(0xffffffffu, s0, o);
            s1 += __shfl_xor_sync(0xffffffffu, s1, o);
        }
        l0 = l0*cr0 + s0;
        l1 = l1*cr1 + s1;

        #pragma unroll
        for (int nt = 0; nt < 8; nt++) {
            O[nt][0] *= cr0; O[nt][1] *= cr0;
            O[nt][2] *= cr1; O[nt][3] *= cr1;
        }
        __syncwarp();

        // ---- O += P @ V ----
        #pragma unroll
        for (int ks = 0; ks < 4; ks++) {
            uint32_t a0 = *(uint32_t*)&Ps[(qr+gy  )*HSTR + ks*16 + 2*gx];
            uint32_t a1 = *(uint32_t*)&Ps[(qr+gy+8)*HSTR + ks*16 + 2*gx];
            uint32_t a2 = *(uint32_t*)&Ps[(qr+gy  )*HSTR + ks*16 + 2*gx + 8];
            uint32_t a3 = *(uint32_t*)&Ps[(qr+gy+8)*HSTR + ks*16 + 2*gx + 8];
            #pragma unroll
            for (int nt = 0; nt < 8; nt++) {
                uint32_t b0 = *(uint32_t*)&Vt[(nt*8+gy)*HSTR + ks*16 + 2*gx];
                uint32_t b1 = *(uint32_t*)&Vt[(nt*8+gy)*HSTR + ks*16 + 2*gx + 8];
                mma_f16(O[nt], a0, a1, a2, a3, b0, b1);
            }
        }
    }

    // ---- epilogue ----
    const int bb = bh >> 4, hh = bh & 15;
    const float inv0 = 1.0f / l0, inv1 = 1.0f / l1;
    const int l_0 = q0 + qr + gy, l_1 = l_0 + 8;
    float* o0 = &out[((size_t)bb*L + l_0)*DIMM + hh*DH];
    float* o1 = &out[((size_t)bb*L + l_1)*DIMM + hh*DH];
    #pragma unroll
    for (int nt = 0; nt < 8; nt++) {
        *(float2*)&o0[nt*8 + 2*gx] = make_float2(O[nt][0]*inv0, O[nt][1]*inv0);
        *(float2*)&o1[nt*8 + 2*gx] = make_float2(O[nt][2]*inv1, O[nt][3]*inv1);
    }
}

// ---------------- launch ----------------
extern "C" void kernel_launch(void* const* d_in, const int* in_sizes, int n_in,
                              void* d_out, int out_size) {
    const float* X  = (const float*)d_in[0];
    const float* Wq = (const float*)d_in[1];
    const float* bq = (const float*)d_in[2];
    const float* Wv = (const float*)d_in[3];
    const float* bv = (const float*)d_in[4];
    const float* ha = (const float*)d_in[5];
    float* out = (float*)d_out;

    cudaFuncSetAttribute(proj_tc_kernel<true>,  cudaFuncAttributeMaxDynamicSharedMemorySize, PROJ_SM_BYTES);
    cudaFuncSetAttribute(proj_tc_kernel<false>, cudaFuncAttributeMaxDynamicSharedMemorySize, PROJ_SM_BYTES);
    cudaFuncSetAttribute(attn_kernel, cudaFuncAttributeMaxDynamicSharedMemorySize, ASM_BYTES);

    init_maxn_kernel<<<1, 32>>>();

    dim3 pg(DIMM/64, TOK/128);
    proj_tc_kernel<true ><<<pg, 256, PROJ_SM_BYTES>>>(X, Wq, bq, ha);  // qk + hash1 fused
    proj_tc_kernel<false><<<pg, 256, PROJ_SM_BYTES>>>(X, Wv, bv, ha);  // v

    hash2_kernel<<<(BH*L)/256, 256>>>(ha);

    dim3 ag(L/128, BH);
    attn_kernel<<<ag, 256, ASM_BYTES>>>(out);
}